// round 14
// baseline (speedup 1.0000x reference)
#include <cuda_runtime.h>
#include <math.h>

#define NB 16
#define NT 2048
#define NF 768
#define NF4 (NF / 4)          // 192
#define EPSV 1e-5f
#define TSPLIT 64
#define TCHUNK (NT / TSPLIT)  // 32
#define NCTA (TSPLIT * NB)    // 1024 total CTAs

// Persistent device state, zero-initialized at module load.
// Invariant: the finalizer CTA restores acc=0, g_ready=0, g_done=0 at the end
// of every launch -> every graph replay starts clean.
__device__ int    g_seq[NB];
__device__ int    g_ready;            // mask preludes: +1 each (16 total)
__device__ int    g_done;             // completion counter (NCTA)
__device__ float4 g_acc1[NB * NF4];   // sum(x)   accumulators (REDG targets)
__device__ float4 g_acc2[NB * NF4];   // sum(x^2) accumulators

// ---------------------------------------------------------------------------
// Single fused kernel — R12 layout with ONE change: __threadfence() is now
// executed by tid 0 only, after __syncthreads() (canonical threadfence-
// reduction pattern), instead of by all 196K threads. Theory: per-thread
// MEMBAR.GPU was what collapsed R10/R12 streaming throughput.
//
// grid = (TSPLIT, NB) = 1024 CTAs x 192 threads, __launch_bounds__(192,7):
// 7x148 = 1036 >= 1024 -> ALL CTAs co-resident -> g_ready spin cannot
// deadlock.
// ---------------------------------------------------------------------------
__global__ void __launch_bounds__(192, 7)
k_all(const float4* __restrict__ x4, const int4* __restrict__ mask4,
      float4* __restrict__ out4) {
    const int bx  = blockIdx.x;        // chunk index ts
    const int b   = blockIdx.y;
    const int tid = threadIdx.x;

    // ---- mask prelude (16 CTAs only; done ~2us in, long before any spin) --
    if (bx < NB && b == 0) {
        int s = 0;
        const int4* mp = mask4 + bx * (NT / 4);
        for (int i = tid; i < NT / 4; i += 192) {
            int4 v = mp[i];
            s += v.x + v.y + v.z + v.w;
        }
#pragma unroll
        for (int off = 16; off; off >>= 1)
            s += __shfl_down_sync(0xffffffffu, s, off);
        __shared__ int ws[6];
        if ((tid & 31) == 0) ws[tid >> 5] = s;
        __syncthreads();
        if (tid == 0) {
            int tot = 0;
#pragma unroll
            for (int w = 0; w < 6; w++) tot += ws[w];
            g_seq[bx] = tot;
            __threadfence();             // tid0-only: release g_seq
            atomicAdd(&g_ready, 1);
        }
        __syncthreads();
    }

    // ---- stream full 32-row chunk, unmasked (R9 loop, untouched) ----
    const int t0 = bx * TCHUNK;
    const float4* p = x4 + ((size_t)b * NT + (size_t)t0) * NF4 + tid;
    float4 s1 = make_float4(0.f, 0.f, 0.f, 0.f);
    float4 s2 = make_float4(0.f, 0.f, 0.f, 0.f);
#pragma unroll 8
    for (int t = 0; t < TCHUNK; t++, p += NF4) {
        float4 v = *p;
        s1.x += v.x; s1.y += v.y; s1.z += v.z; s1.w += v.w;
        s2.x = fmaf(v.x, v.x, s2.x);
        s2.y = fmaf(v.y, v.y, s2.y);
        s2.z = fmaf(v.z, v.z, s2.z);
        s2.w = fmaf(v.w, v.w, s2.w);
    }

    // ---- acquire n (spin passes instantly; deadlock-free: co-resident) ----
    __shared__ int s_n;
    if (tid == 0) {
        while (*(volatile int*)&g_ready < NB) { }
        __threadfence();                 // tid0-only: acquire g_seq
        int smax = 0, sb = 0;
#pragma unroll
        for (int i = 0; i < NB; i++) {
            int v = *(volatile int*)&g_seq[i];
            smax = max(smax, v);
            if (i == b) sb = v;
        }
        // jnp fp32 semantics: divide, multiply by T, round-half-to-even
        const float rel = (float)sb / (float)smax;
        s_n = (int)rintf(rel * (float)NT);
    }
    __syncthreads();
    const int n  = s_n;
    const int t1 = t0 + TCHUNK;

    if (t0 < n) {
        // boundary chunk: subtract rows [n, t1) -- just streamed, L1-hot
        const int ts2 = max(t0, n);      // == t1 for fully-valid chunks
        const float4* q = x4 + ((size_t)b * NT + (size_t)ts2) * NF4 + tid;
        for (int t = ts2; t < t1; t++, q += NF4) {
            float4 v = *q;
            s1.x -= v.x; s1.y -= v.y; s1.z -= v.z; s1.w -= v.w;
            s2.x = fmaf(-v.x, v.x, s2.x);
            s2.y = fmaf(-v.y, v.y, s2.y);
            s2.z = fmaf(-v.z, v.z, s2.z);
            s2.w = fmaf(-v.w, v.w, s2.w);
        }
        // fire-and-forget float atomics into L2-resident accumulators
        float* a1 = (float*)g_acc1;
        float* a2 = (float*)g_acc2;
        const int fb = b * NF + tid * 4;
        atomicAdd(&a1[fb + 0], s1.x);
        atomicAdd(&a1[fb + 1], s1.y);
        atomicAdd(&a1[fb + 2], s1.z);
        atomicAdd(&a1[fb + 3], s1.w);
        atomicAdd(&a2[fb + 0], s2.x);
        atomicAdd(&a2[fb + 1], s2.y);
        atomicAdd(&a2[fb + 2], s2.z);
        atomicAdd(&a2[fb + 3], s2.w);
    }

    // ---- completion counter: canonical pattern, fence in tid0 ONLY ----
    __shared__ int s_last;
    __syncthreads();                     // all CTA's atomics issued
    if (tid == 0) {
        __threadfence();                 // tid0-only: order REDs before ticket
        int old = atomicAdd(&g_done, 1);
        s_last = (old == NCTA - 1);
    }
    __syncthreads();
    if (!s_last) return;

    // ---- last CTA finalizes inline ----
    if (tid == 0) __threadfence();       // acquire all accumulators
    __syncthreads();

    int sq[NB], smax = 0;
#pragma unroll
    for (int i = 0; i < NB; i++) {
        sq[i] = g_seq[i];
        smax = max(smax, sq[i]);
    }

    const float4 zero4 = make_float4(0.f, 0.f, 0.f, 0.f);
#pragma unroll
    for (int j = 0; j < NB; j++) {       // idx4 = j*192+tid -> b = j, f4 = tid
        const int idx4 = j * NF4 + tid;
        float4 v1 = g_acc1[idx4];
        float4 v2 = g_acc2[idx4];

        const float rel = (float)sq[j] / (float)smax;
        const float fn  = rintf(rel * (float)NT);
        const float inv = 1.0f / fn;
        const float idd = 1.0f / (fn - 1.0f);

        float4 mean, sd;
        mean.x = v1.x * inv; mean.y = v1.y * inv;
        mean.z = v1.z * inv; mean.w = v1.w * inv;
        sd.x = sqrtf((v2.x - mean.x * v1.x) * idd) + EPSV;
        sd.y = sqrtf((v2.y - mean.y * v1.y) * idd) + EPSV;
        sd.z = sqrtf((v2.z - mean.z * v1.z) * idd) + EPSV;
        sd.w = sqrtf((v2.w - mean.w * v1.w) * idd) + EPSV;

        // NOTE: reference adds jax-threefry gauss noise in [1e-5, 9e-5] to
        // mean. Omitted: ~5e-5 normalized rel err (budget 1e-3, verified R1).
        out4[j * (2 * NF4) + tid]       = mean;   // [B,1,2F]: mean | std
        out4[j * (2 * NF4) + NF4 + tid] = sd;

        g_acc1[idx4] = zero4;            // restore clean state for next replay
        g_acc2[idx4] = zero4;
    }
    if (tid == 0) {
        g_done  = 0;
        g_ready = 0;
    }
}

// ---------------------------------------------------------------------------
extern "C" void kernel_launch(void* const* d_in, const int* in_sizes, int n_in,
                              void* d_out, int out_size) {
    const float* x    = (const float*)d_in[0];   // [16,2048,768] f32
    const int*   mask = (const int*)d_in[1];     // [16,2048] i32
    float*       out  = (float*)d_out;           // [16,1,1536] f32

    k_all<<<dim3(TSPLIT, NB), 192>>>((const float4*)x, (const int4*)mask,
                                     (float4*)out);
}

// round 16
// speedup vs baseline: 1.6442x; 1.6442x over previous
#include <cuda_runtime.h>
#include <math.h>

#define NB 16
#define NT 2048
#define NF 768
#define NF4 (NF / 4)          // 192
#define EPSV 1e-5f
#define TSPLIT 64
#define TCHUNK (NT / TSPLIT)  // 32
#define NCTA (TSPLIT * NB)    // 1024
#define NFINCTA 512           // CTAs with bx >= 32 double as finalizers

// Persistent device state, zero-initialized at module load.
// Invariant: the last finalize CTA resets g_done/g_fin -> replays start clean.
// Scratch slots are unconditionally overwritten every launch.
__device__ int    g_seq[NB];
__device__ int    g_done;                  // stream-phase completion counter
__device__ int    g_fin;                   // finalize-phase exit counter
__device__ float4 g_S1[NB * NF4 * TSPLIT]; // transposed chunk partials
__device__ float4 g_S2[NB * NF4 * TSPLIT];

// ---------------------------------------------------------------------------
// Single fused kernel = R9's k_main dataflow + ride-along finalize.
// grid = (TSPLIT, NB) = 1024 CTAs x 192 threads; __launch_bounds__(192,7)
// -> 7x148 = 1036 >= 1024: ALL CTAs co-resident, spins cannot deadlock.
//
//   bids 0..15 (bx<16 && b==0): mask-sum prelude -> g_seq[bx]. No flag needed:
//     consumers (finalize warps) are gated by g_done==1024, which implies the
//     prelude finished ~8us earlier.
//   all CTAs: stream 32-row chunk unmasked (R9 loop verbatim), store slot
//     partials (2 STG.128/thread, NO atomics -> R12/R14's REDG burst removed),
//     tid0: threadfence + g_done++ (1024 cheap counter atomics total).
//   bx >= 32 (512 CTAs): spin for g_done==1024 (~CTA spread, ~1us), then run
//     R9's k_final body as 6 warps/CTA over L2-hot scratch. No launch floor.
// ---------------------------------------------------------------------------
__global__ void __launch_bounds__(192, 7)
k_all(const float4* __restrict__ x4, const int4* __restrict__ mask4,
      float4* __restrict__ out4) {
    const int bx  = blockIdx.x;        // chunk index ts
    const int b   = blockIdx.y;
    const int tid = threadIdx.x;

    // ---- mask prelude (16 CTAs, bids 0..15: scheduled first) ----
    if (bx < NB && b == 0) {
        int s = 0;
        const int4* mp = mask4 + bx * (NT / 4);
        for (int i = tid; i < NT / 4; i += 192) {
            int4 v = mp[i];
            s += v.x + v.y + v.z + v.w;
        }
#pragma unroll
        for (int off = 16; off; off >>= 1)
            s += __shfl_down_sync(0xffffffffu, s, off);
        __shared__ int ws[6];
        if ((tid & 31) == 0) ws[tid >> 5] = s;
        __syncthreads();
        if (tid == 0) {
            int tot = 0;
#pragma unroll
            for (int w = 0; w < 6; w++) tot += ws[w];
            g_seq[bx] = tot;
        }
        __syncthreads();
    }

    // ---- stream full 32-row chunk, unmasked (R9 loop, untouched) ----
    {
        const float4* p =
            x4 + ((size_t)b * NT + (size_t)bx * TCHUNK) * NF4 + tid;
        float4 s1 = make_float4(0.f, 0.f, 0.f, 0.f);
        float4 s2 = make_float4(0.f, 0.f, 0.f, 0.f);
#pragma unroll 8
        for (int t = 0; t < TCHUNK; t++, p += NF4) {
            float4 v = *p;
            s1.x += v.x; s1.y += v.y; s1.z += v.z; s1.w += v.w;
            s2.x = fmaf(v.x, v.x, s2.x);
            s2.y = fmaf(v.y, v.y, s2.y);
            s2.z = fmaf(v.z, v.z, s2.z);
            s2.w = fmaf(v.w, v.w, s2.w);
        }
        // transposed slot store (plain STG.128 -> no atomic burst)
        const int idx = (b * NF4 + tid) * TSPLIT + bx;
        g_S1[idx] = s1;
        g_S2[idx] = s2;
    }

    // ---- stream-phase completion ticket (tid0 only) ----
    __syncthreads();                     // CTA's stores all issued
    if (tid == 0) {
        __threadfence();                 // order stores before the ticket
        atomicAdd(&g_done, 1);
    }

    // BUGFIX vs R15: pure stream CTAs are bx < 32 (the old expression
    // evaluated to bx < 0, sending all CTAs into finalize -> negative gw
    // -> illegal memory access).
    if (bx < TSPLIT / 2) return;
    // ---- finalize CTAs (bx in [32,64), 512 CTAs x 6 warps = 3072 warps) ----

    if (tid == 0) {
        while (*(volatile int*)&g_done < NCTA) { }
        __threadfence();                 // acquire all scratch + g_seq
    }
    __syncthreads();

    const int q    = (bx - TSPLIT / 2) * NB + b;           // 0..511
    const int gw   = q * 6 + (tid >> 5);                   // 0..3071
    const int lane = tid & 31;
    const int bf   = gw / NF4;
    const int f4   = gw - bf * NF4;

    // ---- unconditional coalesced slot loads: ts = lane, lane+32 ----
    const float4* S1 = g_S1 + (size_t)gw * TSPLIT;
    const float4* S2 = g_S2 + (size_t)gw * TSPLIT;
    float4 a0 = S1[lane];
    float4 a1 = S1[lane + 32];
    float4 c0 = S2[lane];
    float4 c1 = S2[lane + 32];

    int smax = 0;
#pragma unroll
    for (int i = 0; i < NB; i++) smax = max(smax, g_seq[i]);
    // jnp fp32 semantics: divide, multiply by T, round-half-to-even
    const float rel = (float)g_seq[bf] / (float)smax;
    const int   n   = (int)rintf(rel * (float)NT);
    const int   cb  = n / TCHUNK;
    const int   tb  = cb * TCHUNK;

    float4 s1 = make_float4(0.f, 0.f, 0.f, 0.f);
    float4 s2 = make_float4(0.f, 0.f, 0.f, 0.f);
    if (lane < cb) {
        s1.x += a0.x; s1.y += a0.y; s1.z += a0.z; s1.w += a0.w;
        s2.x += c0.x; s2.y += c0.y; s2.z += c0.z; s2.w += c0.w;
    }
    if (lane + 32 < cb) {
        s1.x += a1.x; s1.y += a1.y; s1.z += a1.z; s1.w += a1.w;
        s2.x += c1.x; s2.y += c1.y; s2.z += c1.z; s2.w += c1.w;
    }

    // ---- boundary row per lane: r = tb + lane (n - tb <= 31), x L2-hot ----
    const int r = tb + lane;
    if (r < n) {
        float4 v = x4[((size_t)bf * NT + (size_t)r) * NF4 + f4];
        s1.x += v.x; s1.y += v.y; s1.z += v.z; s1.w += v.w;
        s2.x = fmaf(v.x, v.x, s2.x);
        s2.y = fmaf(v.y, v.y, s2.y);
        s2.z = fmaf(v.z, v.z, s2.z);
        s2.w = fmaf(v.w, v.w, s2.w);
    }

    // ---- warp tree reduction (8 floats) ----
#pragma unroll
    for (int off = 16; off; off >>= 1) {
        s1.x += __shfl_down_sync(0xffffffffu, s1.x, off);
        s1.y += __shfl_down_sync(0xffffffffu, s1.y, off);
        s1.z += __shfl_down_sync(0xffffffffu, s1.z, off);
        s1.w += __shfl_down_sync(0xffffffffu, s1.w, off);
        s2.x += __shfl_down_sync(0xffffffffu, s2.x, off);
        s2.y += __shfl_down_sync(0xffffffffu, s2.y, off);
        s2.z += __shfl_down_sync(0xffffffffu, s2.z, off);
        s2.w += __shfl_down_sync(0xffffffffu, s2.w, off);
    }

    if (lane == 0) {
        const float fn  = (float)n;
        const float inv = 1.0f / fn;
        const float idd = 1.0f / (fn - 1.0f);

        float4 mean, sd;
        mean.x = s1.x * inv; mean.y = s1.y * inv;
        mean.z = s1.z * inv; mean.w = s1.w * inv;
        sd.x = sqrtf((s2.x - mean.x * s1.x) * idd) + EPSV;
        sd.y = sqrtf((s2.y - mean.y * s1.y) * idd) + EPSV;
        sd.z = sqrtf((s2.z - mean.z * s1.z) * idd) + EPSV;
        sd.w = sqrtf((s2.w - mean.w * s1.w) * idd) + EPSV;

        // NOTE: reference adds jax-threefry gauss noise in [1e-5, 9e-5] to
        // mean. Omitted: ~5e-5 normalized rel err (budget 1e-3, verified R1).
        out4[bf * (2 * NF4) + f4]       = mean;  // [B,1,2F]: mean | std
        out4[bf * (2 * NF4) + NF4 + f4] = sd;
    }

    // ---- replay-safe state reset by the LAST finalize CTA ----
    __syncthreads();
    if (tid == 0) {
        int old = atomicAdd(&g_fin, 1);
        if (old == NFINCTA - 1) {        // everyone else already passed spin
            g_done = 0;
            g_fin  = 0;
        }
    }
}

// ---------------------------------------------------------------------------
extern "C" void kernel_launch(void* const* d_in, const int* in_sizes, int n_in,
                              void* d_out, int out_size) {
    const float* x    = (const float*)d_in[0];   // [16,2048,768] f32
    const int*   mask = (const int*)d_in[1];     // [16,2048] i32
    float*       out  = (float*)d_out;           // [16,1,1536] f32

    k_all<<<dim3(TSPLIT, NB), 192>>>((const float4*)x, (const int4*)mask,
                                     (float4*)out);
}

// round 17
// speedup vs baseline: 1.7690x; 1.0759x over previous
#include <cuda_runtime.h>
#include <math.h>

#define NB 16
#define NT 2048
#define NF 768
#define NF4 (NF / 4)          // 192
#define EPSV 1e-5f
#define TSPLIT 64
#define TCHUNK (NT / TSPLIT)  // 32

// Scratch: every slot unconditionally overwritten each launch -> replay-safe.
// TRANSPOSED layout: g_S1[(b*NF4 + f4) * TSPLIT + ts] so that a k_final warp
// (one per (b,f4)) reads consecutive slots with lane index -> coalesced.
__device__ int    g_seq[NB];
__device__ float4 g_S1[NB * NF4 * TSPLIT];
__device__ float4 g_S2[NB * NF4 * TSPLIT];

// ---------------------------------------------------------------------------
// K1 (fused): blockIdx.x < TSPLIT  -> unmasked 32-row chunk partials
//             blockIdx.x == TSPLIT -> mask row-sum for batch b (hidden under
//             the ~10us of streaming done by the other 1024 CTAs).
// grid = (TSPLIT+1, NB) = 1040 CTAs, 192 threads.  (R9, verbatim)
// ---------------------------------------------------------------------------
__global__ void __launch_bounds__(192)
k_main(const float4* __restrict__ x4, const int4* __restrict__ mask4) {
    const int ts  = blockIdx.x;
    const int b   = blockIdx.y;
    const int tid = threadIdx.x;

    if (ts == TSPLIT) {
        // ---- mask sum for batch b ----
        int s = 0;
        const int4* mp = mask4 + b * (NT / 4);
        for (int i = tid; i < NT / 4; i += 192) {
            int4 v = mp[i];
            s += v.x + v.y + v.z + v.w;
        }
#pragma unroll
        for (int off = 16; off; off >>= 1)
            s += __shfl_down_sync(0xffffffffu, s, off);
        __shared__ int ws[6];
        if ((tid & 31) == 0) ws[tid >> 5] = s;
        __syncthreads();
        if (tid == 0) {
            int tot = 0;
#pragma unroll
            for (int w = 0; w < 6; w++) tot += ws[w];
            g_seq[b] = tot;
        }
        return;
    }

    // ---- unmasked partial over a full 32-row chunk ----
    const float4* p = x4 + ((size_t)b * NT + (size_t)ts * TCHUNK) * NF4 + tid;
    float4 s1 = make_float4(0.f, 0.f, 0.f, 0.f);
    float4 s2 = make_float4(0.f, 0.f, 0.f, 0.f);
#pragma unroll 8
    for (int t = 0; t < TCHUNK; t++, p += NF4) {
        float4 v = *p;
        s1.x += v.x; s1.y += v.y; s1.z += v.z; s1.w += v.w;
        s2.x = fmaf(v.x, v.x, s2.x);
        s2.y = fmaf(v.y, v.y, s2.y);
        s2.z = fmaf(v.z, v.z, s2.z);
        s2.w = fmaf(v.w, v.w, s2.w);
    }
    // transposed slot store: k_final warp reads slots with lane index
    const int idx = (b * NF4 + tid) * TSPLIT + ts;
    g_S1[idx] = s1;
    g_S2[idx] = s2;
}

// ---------------------------------------------------------------------------
// K2: one warp per (b, f4), R9 body — but packed into a SINGLE WAVE:
// grid = 128 CTAs x 768 threads (24 warps) = 3072 warps, all resident at
// once on 148 SMs, so every load chip-wide issues in one latency round
// (R9's 384x8 layout ran 2.6 waves -> ~3 serialized rounds).
// ---------------------------------------------------------------------------
__global__ void __launch_bounds__(768)
k_final(const float4* __restrict__ x4, float4* __restrict__ out4) {
    const int gw   = blockIdx.x * 24 + (threadIdx.x >> 5); // 0..3071 = b*NF4+f4
    const int lane = threadIdx.x & 31;
    const int b    = gw / NF4;
    const int f4   = gw - b * NF4;

    // ---- unconditional coalesced slot loads: ts = lane, lane+32 ----
    const float4* S1 = g_S1 + (size_t)gw * TSPLIT;
    const float4* S2 = g_S2 + (size_t)gw * TSPLIT;
    float4 a0 = S1[lane];
    float4 a1 = S1[lane + 32];
    float4 c0 = S2[lane];
    float4 c1 = S2[lane + 32];

    // ---- n per-thread (16 ints, L2-broadcast; overlaps the loads) ----
    int smax = 0;
#pragma unroll
    for (int i = 0; i < NB; i++) smax = max(smax, g_seq[i]);
    // jnp fp32 semantics: divide, multiply by T, round-half-to-even
    const float rel = (float)g_seq[b] / (float)smax;
    const int   n   = (int)rintf(rel * (float)NT);
    const int   cb  = n / TCHUNK;               // # fully-valid chunks
    const int   tb  = cb * TCHUNK;

    float4 s1 = make_float4(0.f, 0.f, 0.f, 0.f);
    float4 s2 = make_float4(0.f, 0.f, 0.f, 0.f);
    if (lane < cb) {
        s1.x += a0.x; s1.y += a0.y; s1.z += a0.z; s1.w += a0.w;
        s2.x += c0.x; s2.y += c0.y; s2.z += c0.z; s2.w += c0.w;
    }
    if (lane + 32 < cb) {
        s1.x += a1.x; s1.y += a1.y; s1.z += a1.z; s1.w += a1.w;
        s2.x += c1.x; s2.y += c1.y; s2.z += c1.z; s2.w += c1.w;
    }

    // ---- boundary row per lane: r = tb + lane  (n - tb <= 31) ----
    const int r = tb + lane;
    if (r < n) {
        float4 v = x4[((size_t)b * NT + (size_t)r) * NF4 + f4];
        s1.x += v.x; s1.y += v.y; s1.z += v.z; s1.w += v.w;
        s2.x = fmaf(v.x, v.x, s2.x);
        s2.y = fmaf(v.y, v.y, s2.y);
        s2.z = fmaf(v.z, v.z, s2.z);
        s2.w = fmaf(v.w, v.w, s2.w);
    }

    // ---- warp tree reduction (8 floats), no smem / no barrier ----
#pragma unroll
    for (int off = 16; off; off >>= 1) {
        s1.x += __shfl_down_sync(0xffffffffu, s1.x, off);
        s1.y += __shfl_down_sync(0xffffffffu, s1.y, off);
        s1.z += __shfl_down_sync(0xffffffffu, s1.z, off);
        s1.w += __shfl_down_sync(0xffffffffu, s1.w, off);
        s2.x += __shfl_down_sync(0xffffffffu, s2.x, off);
        s2.y += __shfl_down_sync(0xffffffffu, s2.y, off);
        s2.z += __shfl_down_sync(0xffffffffu, s2.z, off);
        s2.w += __shfl_down_sync(0xffffffffu, s2.w, off);
    }

    if (lane == 0) {
        const float fn  = (float)n;
        const float inv = 1.0f / fn;
        const float idd = 1.0f / (fn - 1.0f);

        float4 mean, sd;
        mean.x = s1.x * inv; mean.y = s1.y * inv;
        mean.z = s1.z * inv; mean.w = s1.w * inv;
        sd.x = sqrtf((s2.x - mean.x * s1.x) * idd) + EPSV;
        sd.y = sqrtf((s2.y - mean.y * s1.y) * idd) + EPSV;
        sd.z = sqrtf((s2.z - mean.z * s1.z) * idd) + EPSV;
        sd.w = sqrtf((s2.w - mean.w * s1.w) * idd) + EPSV;

        // NOTE: reference adds jax-threefry gauss noise in [1e-5, 9e-5] to
        // mean. Omitted: ~5e-5 normalized rel err (budget 1e-3, verified R1).
        out4[b * (2 * NF4) + f4]       = mean;   // [B,1,2F]: mean | std
        out4[b * (2 * NF4) + NF4 + f4] = sd;
    }
}

// ---------------------------------------------------------------------------
extern "C" void kernel_launch(void* const* d_in, const int* in_sizes, int n_in,
                              void* d_out, int out_size) {
    const float* x    = (const float*)d_in[0];   // [16,2048,768] f32
    const int*   mask = (const int*)d_in[1];     // [16,2048] i32
    float*       out  = (float*)d_out;           // [16,1,1536] f32

    k_main<<<dim3(TSPLIT + 1, NB), 192>>>((const float4*)x, (const int4*)mask);
    k_final<<<128, 768>>>((const float4*)x, (float4*)out);
}